// round 9
// baseline (speedup 1.0000x reference)
#include <cuda_runtime.h>
#include <cuda.h>
#include <cuda_fp16.h>
#include <math.h>

#define FULLMASK 0xFFFFFFFFu
#define BT    64
#define PDIM  1024
#define CDIM  1024
#define TT    8
#define RANK  32
#define DST   16
#define MROWS (BT * PDIM)
#define KPAD  1088
#define SCALING 4.0f
#define NRP   96

#if defined(__CUDA_ARCH_FEAT_SM103_ALL) || defined(__CUDA_ARCH_FEAT_SM100_ALL) || defined(__CUDA_ARCH_FEAT_SM101_ALL)
#define HAS_TC 1
#endif

__device__ __align__(128) __half g_xh[(size_t)MROWS * KPAD];
__device__ __align__(128) __half g_wh[(size_t)CDIM * KPAD];
__device__ __align__(128) __half g_wch[(size_t)NRP * CDIM];
__device__ float g_rp[(size_t)MROWS * NRP];
__device__ float g_bbe[CDIM];

// ---------------- PTX helpers ----------------
__device__ __forceinline__ uint32_t smem_u32(const void* p) {
    uint32_t a;
    asm("{ .reg .u64 t; cvta.to.shared.u64 t, %1; cvt.u32.u64 %0, t; }" : "=r"(a) : "l"(p));
    return a;
}
#define MBAR_INIT(a, c) asm volatile("mbarrier.init.shared.b64 [%0], %1;" :: "r"(a), "r"(c) : "memory")
#define MBAR_EXPECT_TX(a, b) asm volatile("mbarrier.arrive.expect_tx.shared.b64 _, [%0], %1;" :: "r"(a), "r"(b) : "memory")
#define MBAR_WAIT(a, p) do { \
    asm volatile("{\n\t.reg .pred P1;\n\tWL_%=:\n\t" \
        "mbarrier.try_wait.parity.acquire.cta.shared::cta.b64 P1, [%0], %1, 0x989680;\n\t" \
        "@P1 bra.uni WD_%=;\n\tbra.uni WL_%=;\n\tWD_%=:\n\t}" :: "r"(a), "r"(p) : "memory"); \
} while (0)
#define TMA_LOAD_2D(dst, tm, cx, cy, mb) \
    asm volatile("cp.async.bulk.tensor.2d.shared::cta.global.tile.mbarrier::complete_tx::bytes " \
        "[%0], [%1, {%2, %3}], [%4];" :: "r"(dst), "l"(tm), "r"(cx), "r"(cy), "r"(mb) : "memory")
#define CLUSTER_ARRIVE() asm volatile("barrier.cluster.arrive.aligned;" ::: "memory")
#define CLUSTER_WAIT()   asm volatile("barrier.cluster.wait.aligned;" ::: "memory")

#ifdef HAS_TC
#define TC_ALLOC(s, n) asm volatile("tcgen05.alloc.cta_group::1.sync.aligned.shared::cta.b32 [%0], %1;" :: "r"(s), "r"(n) : "memory")
#define TC_RELINQ()    asm volatile("tcgen05.relinquish_alloc_permit.cta_group::1.sync.aligned;")
#define TC_DEALLOC(t, n) asm volatile("tcgen05.dealloc.cta_group::1.sync.aligned.b32 %0, %1;" :: "r"(t), "r"(n))
#define TC_COMMIT(mb)  asm volatile("tcgen05.commit.cta_group::1.mbarrier::arrive::one.shared::cluster.b64 [%0];" :: "r"(mb) : "memory")
#define TC_ALLOC2(s, n) asm volatile("tcgen05.alloc.cta_group::2.sync.aligned.shared::cta.b32 [%0], %1;" :: "r"(s), "r"(n) : "memory")
#define TC_RELINQ2()    asm volatile("tcgen05.relinquish_alloc_permit.cta_group::2.sync.aligned;")
#define TC_DEALLOC2(t, n) asm volatile("tcgen05.dealloc.cta_group::2.sync.aligned.b32 %0, %1;" :: "r"(t), "r"(n))
#define TC_COMMIT_MC2(mb, mask) \
    asm volatile("tcgen05.commit.cta_group::2.mbarrier::arrive::one.shared::cluster.multicast::cluster.b64 [%0], %1;" \
                 :: "r"(mb), "h"((unsigned short)(mask)) : "memory")
#define TC_FENCE_AFTER() asm volatile("tcgen05.fence::after_thread_sync;" ::: "memory")
#define TC_WAIT_LD()   asm volatile("tcgen05.wait::ld.sync.aligned;" ::: "memory")
#define TMA_LOAD_2D_CG2(dst, tm, cx, cy, mb) \
    asm volatile("{\n\t.reg .b32 lb;\n\tand.b32 lb, %4, 0xFEFFFFFF;\n\t" \
        "cp.async.bulk.tensor.2d.cta_group::2.shared::cluster.global.tile.mbarrier::complete_tx::bytes " \
        "[%0], [%1, {%2, %3}], [lb];\n\t}" :: "r"(dst), "l"(tm), "r"(cx), "r"(cy), "r"(mb) : "memory")

__device__ __forceinline__ void mma_f16_ss(uint32_t d, uint64_t ad, uint64_t bd,
                                           uint32_t idesc, uint32_t accf) {
    asm volatile("{\n\t.reg .pred p;\n\tsetp.ne.u32 p, %4, 0;\n\t"
        "tcgen05.mma.cta_group::1.kind::f16 [%0], %1, %2, %3, {%5,%5,%5,%5}, p;\n\t}"
        :: "r"(d), "l"(ad), "l"(bd), "r"(idesc), "r"(accf), "r"(0u) : "memory");
}
__device__ __forceinline__ void mma_f16_ss_cg2(uint32_t d, uint64_t ad, uint64_t bd,
                                               uint32_t idesc, uint32_t accf) {
    asm volatile("{\n\t.reg .pred p;\n\tsetp.ne.u32 p, %4, 0;\n\t"
        "tcgen05.mma.cta_group::2.kind::f16 [%0], %1, %2, %3, {%5,%5,%5,%5,%5,%5,%5,%5}, p;\n\t}"
        :: "r"(d), "l"(ad), "l"(bd), "r"(idesc), "r"(accf), "r"(0u) : "memory");
}
#define TC_LD_X32(r, t) \
    asm volatile("tcgen05.ld.sync.aligned.32x32b.x32.b32 " \
        "{%0,%1,%2,%3,%4,%5,%6,%7,%8,%9,%10,%11,%12,%13,%14,%15," \
        "%16,%17,%18,%19,%20,%21,%22,%23,%24,%25,%26,%27,%28,%29,%30,%31}, [%32];" \
        : "=r"((r)[0]),"=r"((r)[1]),"=r"((r)[2]),"=r"((r)[3]),"=r"((r)[4]),"=r"((r)[5]),"=r"((r)[6]),"=r"((r)[7]), \
          "=r"((r)[8]),"=r"((r)[9]),"=r"((r)[10]),"=r"((r)[11]),"=r"((r)[12]),"=r"((r)[13]),"=r"((r)[14]),"=r"((r)[15]), \
          "=r"((r)[16]),"=r"((r)[17]),"=r"((r)[18]),"=r"((r)[19]),"=r"((r)[20]),"=r"((r)[21]),"=r"((r)[22]),"=r"((r)[23]), \
          "=r"((r)[24]),"=r"((r)[25]),"=r"((r)[26]),"=r"((r)[27]),"=r"((r)[28]),"=r"((r)[29]),"=r"((r)[30]),"=r"((r)[31]) \
        : "r"(t))
#endif

// SW128 (K=64 rows): layout 2, SBO=64, LBO=1
#define DESC_BASE   ((2ull << 61) | (1ull << 46) | (64ull << 32) | (1ull << 16))
#define MAKE_DESC(a) (DESC_BASE | ((uint64_t)((a) >> 4) & 0x3FFF))
// SW64 (K=32 rows, 64B/row): layout 4, SBO=32, LBO=1
#define DESC_B64    ((4ull << 61) | (1ull << 46) | (32ull << 32) | (1ull << 16))
#define MAKE_D64(a)  (DESC_B64 | ((uint64_t)((a) >> 4) & 0x3FFF))
#define IDESC_BIG 0x10400010u   /* cg2: F32 acc, f16, M=256, N=256 */
#define IDESC_RP  0x8180010u    /* cg1: F32 acc, f16, M=128, N=96  */

// ---------------- k_prep: fused conv + weight builds ----------------
#define CONV_BLKS 32768
#define WB_BLKS   (CDIM * KPAD / 256)
#define WC_BLKS   (NRP * CDIM / 256)
#define BBE_BLKS  4
#define PREP_BLKS (CONV_BLKS + WB_BLKS + WC_BLKS + BBE_BLKS)

__global__ __launch_bounds__(256) void k_prep(const float* __restrict__ x,
                                              const float* __restrict__ Wb,
                                              const float* __restrict__ Wup,
                                              const float* __restrict__ Wout,
                                              const float* __restrict__ Wdown,
                                              const float* __restrict__ Wxp,
                                              const float* __restrict__ bb,
                                              const float* __restrict__ bout) {
    const int bid = blockIdx.x, tid = threadIdx.x;
    if (bid < CONV_BLKS) {
        size_t base = ((size_t)bid * 256 + tid) * 8;
        size_t row = base >> 10, col = base & 1023;
        float4 v0 = *(const float4*)(x + base);
        float4 v1 = *(const float4*)(x + base + 4);
        __half2 h0 = __floats2half2_rn(v0.x, v0.y);
        __half2 h1 = __floats2half2_rn(v0.z, v0.w);
        __half2 h2 = __floats2half2_rn(v1.x, v1.y);
        __half2 h3 = __floats2half2_rn(v1.z, v1.w);
        uint4 u;
        u.x = *(uint32_t*)&h0; u.y = *(uint32_t*)&h1;
        u.z = *(uint32_t*)&h2; u.w = *(uint32_t*)&h3;
        *(uint4*)(g_xh + row * KPAD + col) = u;
    } else if (bid < CONV_BLKS + WB_BLKS) {
        int idx = (bid - CONV_BLKS) * 256 + tid;
        int n = idx / KPAD, c = idx % KPAD;
        float v;
        if (c < 1024) {
            v = Wb[(size_t)n * 1024 + c];
        } else if (c < 1056) {
            int q = c - 1024;
            float s = 0.f;
#pragma unroll
            for (int r = 0; r < RANK; r++)
                s = fmaf(Wup[(size_t)n * RANK + r], Wout[r * RANK + q], s);
            v = SCALING * s;
        } else v = 0.f;
        g_wh[idx] = __float2half_rn(v);
    } else if (bid < CONV_BLKS + WB_BLKS + WC_BLKS) {
        int idx = (bid - CONV_BLKS - WB_BLKS) * 256 + tid;
        int row = idx >> 10, c = idx & 1023;
        float v;
        if (row < RANK) {
            v = Wdown[(size_t)row * CDIM + c];
        } else {
            int i = row - RANK;
            float s = 0.f;
#pragma unroll
            for (int r = 0; r < RANK; r++)
                s = fmaf(Wxp[i * RANK + r], Wdown[(size_t)r * CDIM + c], s);
            v = s;
        }
        g_wch[idx] = __float2half_rn(v);
    } else {
        int n = (bid - CONV_BLKS - WB_BLKS - WC_BLKS) * 256 + tid;
        if (n < CDIM) {
            float s = 0.f;
#pragma unroll
            for (int r = 0; r < RANK; r++)
                s = fmaf(Wup[(size_t)n * RANK + r], bout[r], s);
            g_bbe[n] = bb[n] + SCALING * s;
        }
    }
}

// ---------------- k_red: rp = xh @ Wcomb.T  (M=65536, N=96, K=1024) ----------------
#define R_KCH    64
#define R_NCH    16
#define R_ABYTES (128 * 128)
#define R_BBYTES (NRP * 128)
#define R_STG    (R_ABYTES + R_BBYTES)
#define R_SMEM   (1024 + 3 * R_STG)

__global__ __launch_bounds__(128) void k_red(const __grid_constant__ CUtensorMap tmA,
                                             const __grid_constant__ CUtensorMap tmWc) {
#ifdef HAS_TC
    extern __shared__ __align__(1024) char smem[];
    const uint32_t sbase = smem_u32(smem);
    const uint32_t tslot = sbase;
    const uint32_t fullb = sbase + 16;
    const uint32_t emptb = sbase + 48;
    const uint32_t doneb = sbase + 80;
    const int tid = threadIdx.x, wid = tid >> 5, lane = tid & 31;
    const int m0 = blockIdx.x * 128;

    if (tid == 0) {
        MBAR_INIT(fullb, 1); MBAR_INIT(fullb + 8, 1); MBAR_INIT(fullb + 16, 1);
        MBAR_INIT(emptb, 1); MBAR_INIT(emptb + 8, 1); MBAR_INIT(emptb + 16, 1);
        MBAR_INIT(doneb, 1);
    }
    if (wid == 0) { TC_ALLOC(tslot, 128); TC_RELINQ(); }
    __syncthreads();
    uint32_t tmem;
    asm volatile("ld.shared.b32 %0, [%1];" : "=r"(tmem) : "r"(tslot));

    if (tid == 0) {
        int eph[3] = {1, 1, 1};
        for (int c = 0; c < R_NCH; c++) {
            int s = c % 3;
            MBAR_WAIT(emptb + s * 8, eph[s]); eph[s] ^= 1;
            uint32_t aA = sbase + 1024 + s * R_STG;
            MBAR_EXPECT_TX(fullb + s * 8, R_STG);
            TMA_LOAD_2D(aA, &tmA, c * R_KCH, m0, fullb + s * 8);
            TMA_LOAD_2D(aA + R_ABYTES, &tmWc, c * R_KCH, 0, fullb + s * 8);
        }
    } else if (tid == 33) {
        int fph[3] = {0, 0, 0};
        for (int c = 0; c < R_NCH; c++) {
            int s = c % 3;
            MBAR_WAIT(fullb + s * 8, fph[s]); fph[s] ^= 1;
            uint32_t aA = sbase + 1024 + s * R_STG;
            uint64_t ad = MAKE_DESC(aA), bd = MAKE_DESC(aA + R_ABYTES);
#pragma unroll
            for (int k = 0; k < 4; k++)
                mma_f16_ss(tmem, ad + 2 * k, bd + 2 * k, IDESC_RP, (c | k) != 0);
            TC_COMMIT(emptb + s * 8);
        }
        TC_COMMIT(doneb);
    }

    MBAR_WAIT(doneb, 0);
    TC_FENCE_AFTER();

    float* gr = g_rp + (size_t)(m0 + wid * 32 + lane) * NRP;
#pragma unroll
    for (int cb = 0; cb < 3; cb++) {
        uint32_t r[32];
        TC_LD_X32(r, tmem + cb * 32);
        TC_WAIT_LD();
#pragma unroll
        for (int j = 0; j < 32; j += 4) {
            float4 v;
            v.x = __uint_as_float(r[j]);     v.y = __uint_as_float(r[j + 1]);
            v.z = __uint_as_float(r[j + 2]); v.w = __uint_as_float(r[j + 3]);
            *(float4*)(gr + cb * 32 + j) = v;
        }
    }
    __syncthreads();
    if (wid == 0) TC_DEALLOC(tmem, 128);
#else
    const int tid = threadIdx.x;
    const int m0 = blockIdx.x * 128;
    for (int e = tid; e < 128 * NRP; e += 128) {
        int r = e / NRP, n = e % NRP;
        float acc = 0.f;
        for (int k = 0; k < CDIM; k++)
            acc = fmaf(__half2float(g_xh[(size_t)(m0 + r) * KPAD + k]),
                       __half2float(g_wch[(size_t)n * CDIM + k]), acc);
        g_rp[(size_t)(m0 + r) * NRP + n] = acc;
    }
#endif
}

// ---------------- k_ssm: pure recurrence ----------------
__device__ __forceinline__ float softplusf(float v) {
    return (v > 15.0f) ? v : log1pf(__expf(v));
}

__global__ __launch_bounds__(256) void k_ssm(const float* __restrict__ A_log,
                                             const float* __restrict__ Dp,
                                             const float* __restrict__ bxp) {
    const int tid  = threadIdx.x;
    const int lane = tid & 31;
    const int seq  = (blockIdx.x * blockDim.x + tid) >> 5;
    const int b = seq >> 10, p = seq & 1023;

    float An[DST];
#pragma unroll
    for (int s = 0; s < DST; s++) An[s] = -__expf(__ldg(A_log + lane * 16 + s));
    const float Dpr  = __ldg(Dp + lane);
    const float bx0  = __ldg(bxp + lane);
    const float bx1  = __ldg(bxp + 32 + lane);
    float h[DST];
#pragma unroll
    for (int s = 0; s < DST; s++) h[s] = 0.f;

    for (int t = 0; t < TT; t++) {
        size_t m = (size_t)(b * TT + t) * PDIM + p;
        const float* rp = g_rp + m * NRP;
        float xv = rp[lane];
        float p0 = rp[32 + lane] + bx0;
        float p1 = rp[64 + lane] + bx1;
        float dlt = softplusf(p0);
        float y = Dpr * xv;
#pragma unroll
        for (int s = 0; s < DST; s++) {
            float Bs_ = __shfl_sync(FULLMASK, p1, s);
            float Cs_ = __shfl_sync(FULLMASK, p1, 16 + s);
            float Ab  = __expf(dlt * An[s]);
            h[s] = fmaf(Ab, h[s], dlt * Bs_ * xv);
            y    = fmaf(h[s], Cs_, y);
        }
        g_xh[m * KPAD + 1024 + lane] = __float2half_rn(y);
        g_xh[m * KPAD + 1056 + lane] = __float2half_rn(0.f);
    }
}

// ---------------- k_big: cg2 GEMM, K-chunk 32 (SW64), 6-stage pipeline ----------------
#define KCH       32
#define NCHUNK    34
#define NSTG      6
#define A_BYTES   (128 * 64)              // 8192 (SW64: 64B rows)
#define B_BYTES   (128 * 64)              // 8192
#define STG_BYTES (A_BYTES + B_BYTES)     // 16384
#define SMEM_DYN  (1024 + NSTG * STG_BYTES)  // 99328

__global__ __launch_bounds__(256, 2) __cluster_dims__(2, 1, 1)
void k_big(const __grid_constant__ CUtensorMap tmA,
           const __grid_constant__ CUtensorMap tmB,
           float* __restrict__ out) {
#ifdef HAS_TC
    extern __shared__ __align__(1024) char smem[];
    const uint32_t sbase = smem_u32(smem);
    const uint32_t tslot = sbase;
    const uint32_t fullb = sbase + 16;   // 6 x 8B
    const uint32_t emptb = sbase + 80;   // 6 x 8B
    const uint32_t doneb = sbase + 144;

    const int tid = threadIdx.x, wid = tid >> 5, lane = tid & 31;
    uint32_t rank;
    asm("mov.u32 %0, %%cluster_ctarank;" : "=r"(rank));
    const int mrow = blockIdx.z * 256 + (int)rank * 128;
    const int nrow = blockIdx.y * 256 + (int)rank * 128;

    if (tid == 0) {
#pragma unroll
        for (int s = 0; s < NSTG; s++) {
            MBAR_INIT(fullb + s * 8, 1);
            MBAR_INIT(emptb + s * 8, 1);
        }
        MBAR_INIT(doneb, 1);
    }
    if (wid == 0) { TC_ALLOC2(tslot, 256); TC_RELINQ2(); }
    __syncthreads();
    uint32_t tmem;
    asm volatile("ld.shared.b32 %0, [%1];" : "=r"(tmem) : "r"(tslot));

    CLUSTER_ARRIVE(); CLUSTER_WAIT();

    if (tid == 0) {                 // producer (both CTAs)
        int eph[NSTG] = {1, 1, 1, 1, 1, 1};
        for (int c = 0; c < NCHUNK; c++) {
            int s = c % NSTG;
            MBAR_WAIT(emptb + s * 8, eph[s]); eph[s] ^= 1;
            uint32_t aA = sbase + 1024 + s * STG_BYTES;
            if (rank == 0) MBAR_EXPECT_TX(fullb + s * 8, 2 * STG_BYTES);
            TMA_LOAD_2D_CG2(aA, &tmA, c * KCH, mrow, fullb + s * 8);
            TMA_LOAD_2D_CG2(aA + A_BYTES, &tmB, c * KCH, nrow, fullb + s * 8);
        }
    } else if (tid == 32 && rank == 0) {   // MMA issuer (leader only)
        int fph[NSTG] = {0, 0, 0, 0, 0, 0};
        for (int c = 0; c < NCHUNK; c++) {
            int s = c % NSTG;
            MBAR_WAIT(fullb + s * 8, fph[s]); fph[s] ^= 1;
            uint32_t aA = sbase + 1024 + s * STG_BYTES;
            uint64_t ad = MAKE_D64(aA), bd = MAKE_D64(aA + A_BYTES);
#pragma unroll
            for (int k = 0; k < 2; k++)
                mma_f16_ss_cg2(tmem, ad + 2 * k, bd + 2 * k, IDESC_BIG, (c | k) != 0);
            TC_COMMIT_MC2(emptb + s * 8, 3);
        }
        TC_COMMIT_MC2(doneb, 3);
    }

    MBAR_WAIT(doneb, 0);
    TC_FENCE_AFTER();

    const int row = mrow + (wid & 3) * 32 + lane;
    const int cb0 = (wid >> 2) * 128;
    const int ncol0 = blockIdx.y * 256;
#pragma unroll
    for (int cb = 0; cb < 4; cb++) {
        uint32_t r[32];
        TC_LD_X32(r, tmem + cb0 + cb * 32);
        TC_WAIT_LD();
        const int col = ncol0 + cb0 + cb * 32;
        float* orow = out + (size_t)row * CDIM + col;
#pragma unroll
        for (int j = 0; j < 32; j += 4) {
            float4 v;
            v.x = __uint_as_float(r[j])     + g_bbe[col + j];
            v.y = __uint_as_float(r[j + 1]) + g_bbe[col + j + 1];
            v.z = __uint_as_float(r[j + 2]) + g_bbe[col + j + 2];
            v.w = __uint_as_float(r[j + 3]) + g_bbe[col + j + 3];
            *(float4*)(orow + j) = v;
        }
    }

    __syncthreads();
    if (wid == 0) TC_DEALLOC2(tmem, 256);
    CLUSTER_ARRIVE(); CLUSTER_WAIT();
#else
    const int tid = threadIdx.x;
    const int m0 = blockIdx.z * 256 + blockIdx.x * 128;
    const int n0 = blockIdx.y * 256;
    for (int e = tid; e < 128 * 256; e += 256) {
        int r = e >> 8, c = e & 255;
        const __half2* a = (const __half2*)(g_xh + (size_t)(m0 + r) * KPAD);
        const __half2* w = (const __half2*)(g_wh + (size_t)(n0 + c) * KPAD);
        float acc = 0.f;
        for (int k = 0; k < KPAD / 2; k++) {
            float2 av = __half22float2(a[k]);
            float2 wv = __half22float2(w[k]);
            acc = fmaf(av.x, wv.x, acc);
            acc = fmaf(av.y, wv.y, acc);
        }
        out[(size_t)(m0 + r) * CDIM + n0 + c] = acc + g_bbe[n0 + c];
    }
#endif
}

// ---------------- Host ----------------
typedef CUresult (*EncodeFn)(CUtensorMap*, CUtensorMapDataType, cuuint32_t, void*,
                             const cuuint64_t*, const cuuint64_t*, const cuuint32_t*,
                             const cuuint32_t*, CUtensorMapInterleave, CUtensorMapSwizzle,
                             CUtensorMapL2promotion, CUtensorMapFloatOOBfill);

static void make_map(EncodeFn enc, CUtensorMap* tm, void* ptr, uint64_t d0, uint64_t d1,
                     uint32_t b0, uint32_t b1, CUtensorMapSwizzle sw) {
    cuuint64_t dims[2]    = {d0, d1};
    cuuint64_t strides[1] = {d0 * 2};
    cuuint32_t box[2]     = {b0, b1};
    cuuint32_t es[2]      = {1, 1};
    enc(tm, CU_TENSOR_MAP_DATA_TYPE_FLOAT16, 2, ptr, dims, strides, box, es,
        CU_TENSOR_MAP_INTERLEAVE_NONE, sw,
        CU_TENSOR_MAP_L2_PROMOTION_L2_128B, CU_TENSOR_MAP_FLOAT_OOB_FILL_NONE);
}

extern "C" void kernel_launch(void* const* d_in, const int* in_sizes, int n_in,
                              void* d_out, int out_size) {
    const float* x     = (const float*)d_in[0];
    const float* Wb    = (const float*)d_in[1];
    const float* bb    = (const float*)d_in[2];
    const float* Wdown = (const float*)d_in[3];
    const float* Wup   = (const float*)d_in[4];
    const float* A_log = (const float*)d_in[5];
    const float* Dp    = (const float*)d_in[6];
    const float* Wxp   = (const float*)d_in[7];
    const float* bxp   = (const float*)d_in[8];
    const float* Wout  = (const float*)d_in[9];
    const float* bout  = (const float*)d_in[10];
    float* out = (float*)d_out;

    void* fn = nullptr;
    cudaDriverEntryPointQueryResult qr;
    cudaGetDriverEntryPointByVersion("cuTensorMapEncodeTiled", &fn, CUDART_VERSION,
                                     cudaEnableDefault, &qr);
    EncodeFn enc = (EncodeFn)fn;

    void *xh_ptr, *wh_ptr, *wch_ptr;
    cudaGetSymbolAddress(&xh_ptr,  g_xh);
    cudaGetSymbolAddress(&wh_ptr,  g_wh);
    cudaGetSymbolAddress(&wch_ptr, g_wch);

    CUtensorMap tmA64, tmB64, tmA128, tmWc;
    make_map(enc, &tmA64,  xh_ptr,  KPAD, MROWS, KCH,   128, CU_TENSOR_MAP_SWIZZLE_64B);
    make_map(enc, &tmB64,  wh_ptr,  KPAD, CDIM,  KCH,   128, CU_TENSOR_MAP_SWIZZLE_64B);
    make_map(enc, &tmA128, xh_ptr,  KPAD, MROWS, R_KCH, 128, CU_TENSOR_MAP_SWIZZLE_128B);
    make_map(enc, &tmWc,   wch_ptr, CDIM, NRP,   R_KCH, NRP, CU_TENSOR_MAP_SWIZZLE_128B);

    cudaFuncSetAttribute(k_big, cudaFuncAttributeMaxDynamicSharedMemorySize, SMEM_DYN);
    cudaFuncSetAttribute(k_red, cudaFuncAttributeMaxDynamicSharedMemorySize, R_SMEM);

    k_prep<<<PREP_BLKS, 256>>>(x, Wb, Wup, Wout, Wdown, Wxp, bb, bout);
    k_red<<<MROWS / 128, 128, R_SMEM>>>(tmA128, tmWc);
    k_ssm<<<(MROWS / TT) * 32 / 256, 256>>>(A_log, Dp, bxp);

    dim3 grid(2, CDIM / 256, MROWS / 256);
    k_big<<<grid, 256, SMEM_DYN>>>(tmA64, tmB64, out);
}

// round 10
// speedup vs baseline: 1.0281x; 1.0281x over previous
#include <cuda_runtime.h>
#include <cuda.h>
#include <cuda_fp16.h>
#include <math.h>

#define FULLMASK 0xFFFFFFFFu
#define BT    64
#define PDIM  1024
#define CDIM  1024
#define TT    8
#define RANK  32
#define DST   16
#define MROWS (BT * PDIM)
#define KPAD  1088
#define SCALING 4.0f
#define NRP   96

#if defined(__CUDA_ARCH_FEAT_SM103_ALL) || defined(__CUDA_ARCH_FEAT_SM100_ALL) || defined(__CUDA_ARCH_FEAT_SM101_ALL)
#define HAS_TC 1
#endif

__device__ __align__(128) __half g_xh[(size_t)MROWS * KPAD];
__device__ __align__(128) __half g_wh[(size_t)CDIM * KPAD];
__device__ __align__(128) __half g_wch[(size_t)NRP * CDIM];
__device__ float g_rp[(size_t)MROWS * NRP];
__device__ float g_bbe[CDIM];

// ---------------- PTX helpers ----------------
__device__ __forceinline__ uint32_t smem_u32(const void* p) {
    uint32_t a;
    asm("{ .reg .u64 t; cvta.to.shared.u64 t, %1; cvt.u32.u64 %0, t; }" : "=r"(a) : "l"(p));
    return a;
}
#define MBAR_INIT(a, c) asm volatile("mbarrier.init.shared.b64 [%0], %1;" :: "r"(a), "r"(c) : "memory")
#define MBAR_EXPECT_TX(a, b) asm volatile("mbarrier.arrive.expect_tx.shared.b64 _, [%0], %1;" :: "r"(a), "r"(b) : "memory")
#define MBAR_WAIT(a, p) do { \
    asm volatile("{\n\t.reg .pred P1;\n\tWL_%=:\n\t" \
        "mbarrier.try_wait.parity.acquire.cta.shared::cta.b64 P1, [%0], %1, 0x989680;\n\t" \
        "@P1 bra.uni WD_%=;\n\tbra.uni WL_%=;\n\tWD_%=:\n\t}" :: "r"(a), "r"(p) : "memory"); \
} while (0)
#define TMA_LOAD_2D(dst, tm, cx, cy, mb) \
    asm volatile("cp.async.bulk.tensor.2d.shared::cta.global.tile.mbarrier::complete_tx::bytes " \
        "[%0], [%1, {%2, %3}], [%4];" :: "r"(dst), "l"(tm), "r"(cx), "r"(cy), "r"(mb) : "memory")

#ifdef HAS_TC
#define TC_ALLOC(s, n) asm volatile("tcgen05.alloc.cta_group::1.sync.aligned.shared::cta.b32 [%0], %1;" :: "r"(s), "r"(n) : "memory")
#define TC_RELINQ()    asm volatile("tcgen05.relinquish_alloc_permit.cta_group::1.sync.aligned;")
#define TC_DEALLOC(t, n) asm volatile("tcgen05.dealloc.cta_group::1.sync.aligned.b32 %0, %1;" :: "r"(t), "r"(n))
#define TC_COMMIT(mb)  asm volatile("tcgen05.commit.cta_group::1.mbarrier::arrive::one.shared::cluster.b64 [%0];" :: "r"(mb) : "memory")
#define TC_FENCE_AFTER() asm volatile("tcgen05.fence::after_thread_sync;" ::: "memory")
#define TC_WAIT_LD()   asm volatile("tcgen05.wait::ld.sync.aligned;" ::: "memory")

__device__ __forceinline__ void mma_f16_ss(uint32_t d, uint64_t ad, uint64_t bd,
                                           uint32_t idesc, uint32_t accf) {
    asm volatile("{\n\t.reg .pred p;\n\tsetp.ne.u32 p, %4, 0;\n\t"
        "tcgen05.mma.cta_group::1.kind::f16 [%0], %1, %2, %3, {%5,%5,%5,%5}, p;\n\t}"
        :: "r"(d), "l"(ad), "l"(bd), "r"(idesc), "r"(accf), "r"(0u) : "memory");
}
#define TC_LD_X32(r, t) \
    asm volatile("tcgen05.ld.sync.aligned.32x32b.x32.b32 " \
        "{%0,%1,%2,%3,%4,%5,%6,%7,%8,%9,%10,%11,%12,%13,%14,%15," \
        "%16,%17,%18,%19,%20,%21,%22,%23,%24,%25,%26,%27,%28,%29,%30,%31}, [%32];" \
        : "=r"((r)[0]),"=r"((r)[1]),"=r"((r)[2]),"=r"((r)[3]),"=r"((r)[4]),"=r"((r)[5]),"=r"((r)[6]),"=r"((r)[7]), \
          "=r"((r)[8]),"=r"((r)[9]),"=r"((r)[10]),"=r"((r)[11]),"=r"((r)[12]),"=r"((r)[13]),"=r"((r)[14]),"=r"((r)[15]), \
          "=r"((r)[16]),"=r"((r)[17]),"=r"((r)[18]),"=r"((r)[19]),"=r"((r)[20]),"=r"((r)[21]),"=r"((r)[22]),"=r"((r)[23]), \
          "=r"((r)[24]),"=r"((r)[25]),"=r"((r)[26]),"=r"((r)[27]),"=r"((r)[28]),"=r"((r)[29]),"=r"((r)[30]),"=r"((r)[31]) \
        : "r"(t))
#endif

#define DESC_BASE ((2ull << 61) | (1ull << 46) | (64ull << 32) | (1ull << 16))
#define MAKE_DESC(a) (DESC_BASE | ((uint64_t)((a) >> 4) & 0x3FFF))
#define IDESC_BIG 0x8400010u    /* cg1: F32 acc, f16, M=128, N=256 */
#define IDESC_RP  0x8180010u    /* cg1: F32 acc, f16, M=128, N=96  */

// ---------------- k_prep: fused conv + weight builds ----------------
#define CONV_BLKS 32768
#define WB_BLKS   (CDIM * KPAD / 256)
#define WC_BLKS   (NRP * CDIM / 256)
#define BBE_BLKS  4
#define PREP_BLKS (CONV_BLKS + WB_BLKS + WC_BLKS + BBE_BLKS)

__global__ __launch_bounds__(256) void k_prep(const float* __restrict__ x,
                                              const float* __restrict__ Wb,
                                              const float* __restrict__ Wup,
                                              const float* __restrict__ Wout,
                                              const float* __restrict__ Wdown,
                                              const float* __restrict__ Wxp,
                                              const float* __restrict__ bb,
                                              const float* __restrict__ bout) {
    const int bid = blockIdx.x, tid = threadIdx.x;
    if (bid < CONV_BLKS) {
        size_t base = ((size_t)bid * 256 + tid) * 8;
        size_t row = base >> 10, col = base & 1023;
        float4 v0 = *(const float4*)(x + base);
        float4 v1 = *(const float4*)(x + base + 4);
        __half2 h0 = __floats2half2_rn(v0.x, v0.y);
        __half2 h1 = __floats2half2_rn(v0.z, v0.w);
        __half2 h2 = __floats2half2_rn(v1.x, v1.y);
        __half2 h3 = __floats2half2_rn(v1.z, v1.w);
        uint4 u;
        u.x = *(uint32_t*)&h0; u.y = *(uint32_t*)&h1;
        u.z = *(uint32_t*)&h2; u.w = *(uint32_t*)&h3;
        *(uint4*)(g_xh + row * KPAD + col) = u;
    } else if (bid < CONV_BLKS + WB_BLKS) {
        int idx = (bid - CONV_BLKS) * 256 + tid;
        int n = idx / KPAD, c = idx % KPAD;
        float v;
        if (c < 1024) {
            v = Wb[(size_t)n * 1024 + c];
        } else if (c < 1056) {
            int q = c - 1024;
            float s = 0.f;
#pragma unroll
            for (int r = 0; r < RANK; r++)
                s = fmaf(Wup[(size_t)n * RANK + r], Wout[r * RANK + q], s);
            v = SCALING * s;
        } else v = 0.f;
        g_wh[idx] = __float2half_rn(v);
    } else if (bid < CONV_BLKS + WB_BLKS + WC_BLKS) {
        int idx = (bid - CONV_BLKS - WB_BLKS) * 256 + tid;
        int row = idx >> 10, c = idx & 1023;
        float v;
        if (row < RANK) {
            v = Wdown[(size_t)row * CDIM + c];
        } else {
            int i = row - RANK;
            float s = 0.f;
#pragma unroll
            for (int r = 0; r < RANK; r++)
                s = fmaf(Wxp[i * RANK + r], Wdown[(size_t)r * CDIM + c], s);
            v = s;
        }
        g_wch[idx] = __float2half_rn(v);
    } else {
        int n = (bid - CONV_BLKS - WB_BLKS - WC_BLKS) * 256 + tid;
        if (n < CDIM) {
            float s = 0.f;
#pragma unroll
            for (int r = 0; r < RANK; r++)
                s = fmaf(Wup[(size_t)n * RANK + r], bout[r], s);
            g_bbe[n] = bb[n] + SCALING * s;
        }
    }
}

// ---------------- k_red: rp = xh @ Wcomb.T  (M=65536, N=96, K=1024) ----------------
#define R_KCH    64
#define R_NCH    16
#define R_ABYTES (128 * 128)
#define R_BBYTES (NRP * 128)
#define R_STG    (R_ABYTES + R_BBYTES)
#define R_SMEM   (1024 + 3 * R_STG)

__global__ __launch_bounds__(128) void k_red(const __grid_constant__ CUtensorMap tmA,
                                             const __grid_constant__ CUtensorMap tmWc) {
#ifdef HAS_TC
    extern __shared__ __align__(1024) char smem[];
    const uint32_t sbase = smem_u32(smem);
    const uint32_t tslot = sbase;
    const uint32_t fullb = sbase + 16;
    const uint32_t emptb = sbase + 48;
    const uint32_t doneb = sbase + 80;
    const int tid = threadIdx.x, wid = tid >> 5, lane = tid & 31;
    const int m0 = blockIdx.x * 128;

    if (tid == 0) {
        MBAR_INIT(fullb, 1); MBAR_INIT(fullb + 8, 1); MBAR_INIT(fullb + 16, 1);
        MBAR_INIT(emptb, 1); MBAR_INIT(emptb + 8, 1); MBAR_INIT(emptb + 16, 1);
        MBAR_INIT(doneb, 1);
    }
    if (wid == 0) { TC_ALLOC(tslot, 128); TC_RELINQ(); }
    __syncthreads();
    uint32_t tmem;
    asm volatile("ld.shared.b32 %0, [%1];" : "=r"(tmem) : "r"(tslot));

    if (tid == 0) {
        int eph[3] = {1, 1, 1};
        for (int c = 0; c < R_NCH; c++) {
            int s = c % 3;
            MBAR_WAIT(emptb + s * 8, eph[s]); eph[s] ^= 1;
            uint32_t aA = sbase + 1024 + s * R_STG;
            MBAR_EXPECT_TX(fullb + s * 8, R_STG);
            TMA_LOAD_2D(aA, &tmA, c * R_KCH, m0, fullb + s * 8);
            TMA_LOAD_2D(aA + R_ABYTES, &tmWc, c * R_KCH, 0, fullb + s * 8);
        }
    } else if (tid == 33) {
        int fph[3] = {0, 0, 0};
        for (int c = 0; c < R_NCH; c++) {
            int s = c % 3;
            MBAR_WAIT(fullb + s * 8, fph[s]); fph[s] ^= 1;
            uint32_t aA = sbase + 1024 + s * R_STG;
            uint64_t ad = MAKE_DESC(aA), bd = MAKE_DESC(aA + R_ABYTES);
#pragma unroll
            for (int k = 0; k < 4; k++)
                mma_f16_ss(tmem, ad + 2 * k, bd + 2 * k, IDESC_RP, (c | k) != 0);
            TC_COMMIT(emptb + s * 8);
        }
        TC_COMMIT(doneb);
    }

    MBAR_WAIT(doneb, 0);
    TC_FENCE_AFTER();

    float* gr = g_rp + (size_t)(m0 + wid * 32 + lane) * NRP;
#pragma unroll
    for (int cb = 0; cb < 3; cb++) {
        uint32_t r[32];
        TC_LD_X32(r, tmem + cb * 32);
        TC_WAIT_LD();
#pragma unroll
        for (int j = 0; j < 32; j += 4) {
            float4 v;
            v.x = __uint_as_float(r[j]);     v.y = __uint_as_float(r[j + 1]);
            v.z = __uint_as_float(r[j + 2]); v.w = __uint_as_float(r[j + 3]);
            *(float4*)(gr + cb * 32 + j) = v;
        }
    }
    __syncthreads();
    if (wid == 0) TC_DEALLOC(tmem, 128);
#else
    const int tid = threadIdx.x;
    const int m0 = blockIdx.x * 128;
    for (int e = tid; e < 128 * NRP; e += 128) {
        int r = e / NRP, n = e % NRP;
        float acc = 0.f;
        for (int k = 0; k < CDIM; k++)
            acc = fmaf(__half2float(g_xh[(size_t)(m0 + r) * KPAD + k]),
                       __half2float(g_wch[(size_t)n * CDIM + k]), acc);
        g_rp[(size_t)(m0 + r) * NRP + n] = acc;
    }
#endif
}

// ---------------- k_ssm: pure recurrence ----------------
__device__ __forceinline__ float softplusf(float v) {
    return (v > 15.0f) ? v : log1pf(__expf(v));
}

__global__ __launch_bounds__(256) void k_ssm(const float* __restrict__ A_log,
                                             const float* __restrict__ Dp,
                                             const float* __restrict__ bxp) {
    const int tid  = threadIdx.x;
    const int lane = tid & 31;
    const int seq  = (blockIdx.x * blockDim.x + tid) >> 5;
    const int b = seq >> 10, p = seq & 1023;

    float An[DST];
#pragma unroll
    for (int s = 0; s < DST; s++) An[s] = -__expf(__ldg(A_log + lane * 16 + s));
    const float Dpr  = __ldg(Dp + lane);
    const float bx0  = __ldg(bxp + lane);
    const float bx1  = __ldg(bxp + 32 + lane);
    float h[DST];
#pragma unroll
    for (int s = 0; s < DST; s++) h[s] = 0.f;

    for (int t = 0; t < TT; t++) {
        size_t m = (size_t)(b * TT + t) * PDIM + p;
        const float* rp = g_rp + m * NRP;
        float xv = rp[lane];
        float p0 = rp[32 + lane] + bx0;
        float p1 = rp[64 + lane] + bx1;
        float dlt = softplusf(p0);
        float y = Dpr * xv;
#pragma unroll
        for (int s = 0; s < DST; s++) {
            float Bs_ = __shfl_sync(FULLMASK, p1, s);
            float Cs_ = __shfl_sync(FULLMASK, p1, 16 + s);
            float Ab  = __expf(dlt * An[s]);
            h[s] = fmaf(Ab, h[s], dlt * Bs_ * xv);
            y    = fmaf(h[s], Cs_, y);
        }
        g_xh[m * KPAD + 1024 + lane] = __float2half_rn(y);
        g_xh[m * KPAD + 1056 + lane] = __float2half_rn(0.f);
    }
}

// ---------------- k_big: cg1 GEMM (R5 proven config), out = A @ B^T + bbe ----------------
#define KCH       64
#define NCHUNK    17
#define A_BYTES   (128 * 128)
#define B_BYTES   (256 * 128)
#define STG_BYTES (A_BYTES + B_BYTES)      // 49152
#define SMEM_DYN  (1024 + 2 * STG_BYTES)   // 99328

__global__ __launch_bounds__(256, 2) void k_big(const __grid_constant__ CUtensorMap tmA,
                                                const __grid_constant__ CUtensorMap tmB,
                                                float* __restrict__ out) {
#ifdef HAS_TC
    extern __shared__ __align__(1024) char smem[];
    const uint32_t sbase = smem_u32(smem);
    const uint32_t tslot = sbase;
    const uint32_t fullb = sbase + 16;
    const uint32_t emptb = sbase + 32;
    const uint32_t doneb = sbase + 48;

    const int tid = threadIdx.x;
    const int wid = tid >> 5, lane = tid & 31;
    const int m0 = blockIdx.y * 128;
    const int n0 = blockIdx.x * 256;

    if (tid == 0) {
        MBAR_INIT(fullb, 1); MBAR_INIT(fullb + 8, 1);
        MBAR_INIT(emptb, 1); MBAR_INIT(emptb + 8, 1);
        MBAR_INIT(doneb, 1);
    }
    if (wid == 0) { TC_ALLOC(tslot, 256); TC_RELINQ(); }
    __syncthreads();
    uint32_t tmem;
    asm volatile("ld.shared.b32 %0, [%1];" : "=r"(tmem) : "r"(tslot));

    if (tid == 0) {                 // producer
        int eph[2] = {1, 1};
        for (int c = 0; c < NCHUNK; c++) {
            int s = c & 1;
            MBAR_WAIT(emptb + s * 8, eph[s]); eph[s] ^= 1;
            uint32_t aA = sbase + 1024 + s * STG_BYTES;
            MBAR_EXPECT_TX(fullb + s * 8, STG_BYTES);
            TMA_LOAD_2D(aA, &tmA, c * KCH, m0, fullb + s * 8);
            TMA_LOAD_2D(aA + A_BYTES, &tmB, c * KCH, n0, fullb + s * 8);
        }
    } else if (tid == 32) {         // MMA issuer
        int fph[2] = {0, 0};
        for (int c = 0; c < NCHUNK; c++) {
            int s = c & 1;
            MBAR_WAIT(fullb + s * 8, fph[s]); fph[s] ^= 1;
            uint32_t aA = sbase + 1024 + s * STG_BYTES;
            uint64_t ad = MAKE_DESC(aA), bd = MAKE_DESC(aA + A_BYTES);
#pragma unroll
            for (int k = 0; k < 4; k++)
                mma_f16_ss(tmem, ad + 2 * k, bd + 2 * k, IDESC_BIG, (c | k) != 0);
            TC_COMMIT(emptb + s * 8);
        }
        TC_COMMIT(doneb);
    }

    MBAR_WAIT(doneb, 0);
    TC_FENCE_AFTER();

    const int row = m0 + (wid & 3) * 32 + lane;
    const int cb0 = (wid >> 2) * 128;
#pragma unroll
    for (int cb = 0; cb < 4; cb++) {
        uint32_t r[32];
        TC_LD_X32(r, tmem + cb0 + cb * 32);
        TC_WAIT_LD();
        const int col = n0 + cb0 + cb * 32;
        float* orow = out + (size_t)row * CDIM + col;
#pragma unroll
        for (int j = 0; j < 32; j += 4) {
            float4 v;
            v.x = __uint_as_float(r[j])     + g_bbe[col + j];
            v.y = __uint_as_float(r[j + 1]) + g_bbe[col + j + 1];
            v.z = __uint_as_float(r[j + 2]) + g_bbe[col + j + 2];
            v.w = __uint_as_float(r[j + 3]) + g_bbe[col + j + 3];
            *(float4*)(orow + j) = v;
        }
    }

    __syncthreads();
    if (wid == 0) TC_DEALLOC(tmem, 256);
#else
    const int tid = threadIdx.x;
    const int m0 = blockIdx.y * 128;
    const int n0 = blockIdx.x * 256;
    for (int e = tid; e < 128 * 256; e += 256) {
        int r = e >> 8, c = e & 255;
        const __half2* a = (const __half2*)(g_xh + (size_t)(m0 + r) * KPAD);
        const __half2* w = (const __half2*)(g_wh + (size_t)(n0 + c) * KPAD);
        float acc = 0.f;
        for (int k = 0; k < KPAD / 2; k++) {
            float2 av = __half22float2(a[k]);
            float2 wv = __half22float2(w[k]);
            acc = fmaf(av.x, wv.x, acc);
            acc = fmaf(av.y, wv.y, acc);
        }
        out[(size_t)(m0 + r) * CDIM + n0 + c] = acc + g_bbe[n0 + c];
    }
#endif
}

// ---------------- Host ----------------
typedef CUresult (*EncodeFn)(CUtensorMap*, CUtensorMapDataType, cuuint32_t, void*,
                             const cuuint64_t*, const cuuint64_t*, const cuuint32_t*,
                             const cuuint32_t*, CUtensorMapInterleave, CUtensorMapSwizzle,
                             CUtensorMapL2promotion, CUtensorMapFloatOOBfill);

static void make_map(EncodeFn enc, CUtensorMap* tm, void* ptr, uint64_t d0, uint64_t d1,
                     uint32_t b0, uint32_t b1) {
    cuuint64_t dims[2]    = {d0, d1};
    cuuint64_t strides[1] = {d0 * 2};
    cuuint32_t box[2]     = {b0, b1};
    cuuint32_t es[2]      = {1, 1};
    enc(tm, CU_TENSOR_MAP_DATA_TYPE_FLOAT16, 2, ptr, dims, strides, box, es,
        CU_TENSOR_MAP_INTERLEAVE_NONE, CU_TENSOR_MAP_SWIZZLE_128B,
        CU_TENSOR_MAP_L2_PROMOTION_L2_128B, CU_TENSOR_MAP_FLOAT_OOB_FILL_NONE);
}

extern "C" void kernel_launch(void* const* d_in, const int* in_sizes, int n_in,
                              void* d_out, int out_size) {
    const float* x     = (const float*)d_in[0];
    const float* Wb    = (const float*)d_in[1];
    const float* bb    = (const float*)d_in[2];
    const float* Wdown = (const float*)d_in[3];
    const float* Wup   = (const float*)d_in[4];
    const float* A_log = (const float*)d_in[5];
    const float* Dp    = (const float*)d_in[6];
    const float* Wxp   = (const float*)d_in[7];
    const float* bxp   = (const float*)d_in[8];
    const float* Wout  = (const float*)d_in[9];
    const float* bout  = (const float*)d_in[10];
    float* out = (float*)d_out;

    void* fn = nullptr;
    cudaDriverEntryPointQueryResult qr;
    cudaGetDriverEntryPointByVersion("cuTensorMapEncodeTiled", &fn, CUDART_VERSION,
                                     cudaEnableDefault, &qr);
    EncodeFn enc = (EncodeFn)fn;

    void *xh_ptr, *wh_ptr, *wch_ptr;
    cudaGetSymbolAddress(&xh_ptr,  g_xh);
    cudaGetSymbolAddress(&wh_ptr,  g_wh);
    cudaGetSymbolAddress(&wch_ptr, g_wch);

    CUtensorMap tmA, tmB, tmWc;
    make_map(enc, &tmA,  xh_ptr,  KPAD, MROWS, KCH,   128);
    make_map(enc, &tmB,  wh_ptr,  KPAD, CDIM,  KCH,   256);
    make_map(enc, &tmWc, wch_ptr, CDIM, NRP,   R_KCH, NRP);

    cudaFuncSetAttribute(k_big, cudaFuncAttributeMaxDynamicSharedMemorySize, SMEM_DYN);
    cudaFuncSetAttribute(k_red, cudaFuncAttributeMaxDynamicSharedMemorySize, R_SMEM);

    k_prep<<<PREP_BLKS, 256>>>(x, Wb, Wup, Wout, Wdown, Wxp, bb, bout);
    k_red<<<MROWS / 128, 128, R_SMEM>>>(tmA, tmWc);
    k_ssm<<<(MROWS / TT) * 32 / 256, 256>>>(A_log, Dp, bxp);

    dim3 grid(CDIM / 256, MROWS / 128);
    k_big<<<grid, 256, SMEM_DYN>>>(tmA, tmB, out);
}